// round 12
// baseline (speedup 1.0000x reference)
#include <cuda_runtime.h>
#include <cuda_bf16.h>
#include <cstdint>
#include <cstddef>

#define D_DIM   64
#define KC      1024
#define TOKB    4096
#define NTOK    65536
#define BM      64            // tokens per CTA
#define NTILES  16
#define NBLK    (NTOK / BM)   // 1024
#define LOSS_OFF 4194304
#define IDX_OFF  4194305
#define CLAMPV  1.0e6f
#define TILE_BYTES 8192       // one B tile: 64 codes x 128B (bf16 e, no split)

// smem layout (bytes)
#define OFF_ZSQ   0        // 64*4 -> 256
#define OFF_ESQ   256      // 1024*4 -> 4352
#define OFF_FBV   4352     // 2*64*4 -> 4864
#define OFF_FBI   4864     // -> 5376
#define OFF_FB2   5376     // -> 5888
#define OFF_SIDX  5888     // 64*4 -> 6144
#define OFF_WSUM  6144     // 8*4
#define OFF_ZVEC  6208     // 64*4 -> 6464
#define OFF_REDV  6464     // 8*4
#define OFF_REDI  6496     // 8*4
#define OFF_FLAGW 6528     // 2*4
#define OFF_MGN   6560     // 64*4 -> 6816  (per-token certified margin)
#define OFF_MBAR  6848     // 4 mbarriers * 8B
#define OFF_AST   8192     // 2 parts * 8192 = 16384
#define OFF_B     24576    // 4 stages * 8192 = 32768
#define SMEM_TOTAL 57344

__device__ float g_embT[D_DIM * KC];
__device__ float g_esq[KC];
__device__ float g_part[NBLK];
// Pre-swizzled bf16 B tile images: [tile(16)][row(64)*128B], ldmatrix-ready
__device__ __align__(128) unsigned char g_Bsw[NTILES * TILE_BYTES];

// ---------------- helpers ----------------
__device__ __forceinline__ uint32_t smem_u32(const void* p) {
    uint32_t a;
    asm("{ .reg .u64 t; cvta.to.shared.u64 t, %1; cvt.u32.u64 %0, t; }" : "=r"(a) : "l"(p));
    return a;
}
__device__ __forceinline__ void split2(float z, __nv_bfloat16& a, __nv_bfloat16& b) {
    a = __float2bfloat16(z);
    b = __float2bfloat16(z - __bfloat162float(a));
}
__device__ __forceinline__ void ldsm4(uint32_t* r, uint32_t a) {
    asm volatile("ldmatrix.sync.aligned.m8n8.x4.shared.b16 {%0,%1,%2,%3}, [%4];"
                 : "=r"(r[0]), "=r"(r[1]), "=r"(r[2]), "=r"(r[3]) : "r"(a));
}
__device__ __forceinline__ void mma16816(float* c, const uint32_t* a, const uint32_t* b) {
    asm volatile(
        "mma.sync.aligned.m16n8k16.row.col.f32.bf16.bf16.f32 "
        "{%0,%1,%2,%3}, {%4,%5,%6,%7}, {%8,%9}, {%0,%1,%2,%3};"
        : "+f"(c[0]), "+f"(c[1]), "+f"(c[2]), "+f"(c[3])
        : "r"(a[0]), "r"(a[1]), "r"(a[2]), "r"(a[3]), "r"(b[0]), "r"(b[1]));
}
__device__ __forceinline__ void mbar_init(uint32_t mbar, uint32_t cnt) {
    asm volatile("mbarrier.init.shared.b64 [%0], %1;" :: "r"(mbar), "r"(cnt) : "memory");
}
__device__ __forceinline__ void mbar_expect_tx(uint32_t mbar, uint32_t bytes) {
    asm volatile("mbarrier.arrive.expect_tx.shared.b64 _, [%0], %1;"
                 :: "r"(mbar), "r"(bytes) : "memory");
}
__device__ __forceinline__ void bulk_g2s(uint32_t dst, const void* src, uint32_t bytes,
                                         uint32_t mbar) {
    asm volatile(
        "cp.async.bulk.shared::cta.global.mbarrier::complete_tx::bytes [%0], [%1], %2, [%3];"
        :: "r"(dst), "l"(src), "r"(bytes), "r"(mbar) : "memory");
}
__device__ __forceinline__ void mbar_wait(uint32_t mbar, uint32_t parity) {
    asm volatile(
        "{\n\t.reg .pred P;\n\t"
        "W_%=:\n\tmbarrier.try_wait.parity.acquire.cta.shared::cta.b64 P, [%0], %1, 0x989680;\n\t"
        "@P bra.uni D_%=;\n\tbra.uni W_%=;\n\tD_%=:\n\t}"
        :: "r"(mbar), "r"(parity) : "memory");
}

// ---------------- Prep: transpose, norms, bf16 e into swizzled tiles --------
__global__ void vq_prep_kernel(const float* __restrict__ emb) {
    int idx = blockIdx.x * blockDim.x + threadIdx.x;   // 0..65535
    int n = idx >> 6, d = idx & 63;
    float v = emb[idx];                 // emb[n*64 + d] (coalesced)
    g_embT[d * KC + n] = v;
    int t = n >> 6, nl = n & 63;
    uint32_t off = (uint32_t)(t * TILE_BYTES + nl * 128
                 + (((d >> 3) ^ (nl & 7)) << 4) + (d & 7) * 2);
    *(__nv_bfloat16*)(g_Bsw + off) = __float2bfloat16(v);
    if (idx < KC) {
        const float4* e4 = (const float4*)(emb + (size_t)idx * D_DIM);
        float s = 0.f;
        #pragma unroll
        for (int i = 0; i < 16; i++) {
            float4 w = e4[i];
            s += w.x * w.x + w.y * w.y + w.z * w.z + w.w * w.w;
        }
        g_esq[idx] = fminf(s, CLAMPV);
    }
}

// ---------------- Main: split-z x bf16-e GEMM + certified-margin rescue -----
__global__ void __launch_bounds__(256, 2) vq_main_kernel(
    const float* __restrict__ z_e, float* __restrict__ out)
{
    extern __shared__ __align__(128) unsigned char smem[];
    const uint32_t sbase = smem_u32(smem);
    const int tid = threadIdx.x, wid = tid >> 5, lane = tid & 31;
    const int rowg = wid >> 1;            // 0..3 : 16 rows each
    const int colg = wid & 1;             // 0..1 : 32 cols each
    const int b = blockIdx.x >> 6, t0 = (blockIdx.x & 63) << 6;
    const float* zb = z_e + (size_t)b * D_DIM * TOKB + t0;

    float* s_zsq = (float*)(smem + OFF_ZSQ);
    float* s_esq = (float*)(smem + OFF_ESQ);
    float* s_mgn = (float*)(smem + OFF_MGN);
    const uint32_t mb0 = sbase + OFF_MBAR;

    if (tid == 0) {
        #pragma unroll
        for (int s = 0; s < 4; s++) mbar_init(mb0 + s * 8, 1);
    }
    __syncthreads();
    if (tid == 0) {
        #pragma unroll
        for (int p = 0; p < 3; p++) {
            mbar_expect_tx(mb0 + p * 8, TILE_BYTES);
            bulk_g2s(sbase + OFF_B + p * TILE_BYTES, g_Bsw + (size_t)p * TILE_BYTES,
                     TILE_BYTES, mb0 + p * 8);
        }
    }

    // A staging: z split into 2 bf16 parts, [m(64)][k(64)] 128B rows, swizzled
    for (int i = tid; i < D_DIM * BM; i += 256) {
        int m = i & 63, d = i >> 6;
        __nv_bfloat16 va, vb;
        split2(zb[(size_t)d * TOKB + m], va, vb);
        uint32_t off = (uint32_t)(m * 128 + (((d >> 3) ^ (m & 7)) << 4) + (d & 7) * 2);
        *(__nv_bfloat16*)(smem + OFF_AST + off) = va;
        *(__nv_bfloat16*)(smem + OFF_AST + 8192 + off) = vb;
    }
    if (tid < BM) {   // exact ref zsq + certified margin (dropped-term bound)
        float s = 0.f, sa = 0.f;
        for (int d = 0; d < D_DIM; d++) {
            float z = zb[(size_t)d * TOKB + tid];
            s = fmaf(z, z, s);
            sa += fabsf(z);
        }
        s_zsq[tid] = fminf(s, CLAMPV);
        // |dist error| <= 2 * sum|z_d| * 2e-6 (|e - bf16(e)| < 2e-6) + slack
        s_mgn[tid] = fmaf(4.2e-6f, sa, 2.0e-5f);
    }
    for (int i = tid; i < KC; i += 256) s_esq[i] = g_esq[i];
    __syncthreads();

    // ---- Hoist A fragments (tile-invariant): afr[part][ks][4]
    const uint32_t xr  = (uint32_t)(lane & 7);
    const uint32_t aHi = (uint32_t)(lane >> 4);
    const uint32_t bHi = (uint32_t)((lane >> 3) & 1);
    const uint32_t rowByteA = (uint32_t)((rowg * 16 + (lane & 15)) * 128);
    uint32_t afr[2][4][4];
    #pragma unroll
    for (int p = 0; p < 2; p++)
        #pragma unroll
        for (int ks = 0; ks < 4; ks++) {
            uint32_t ca = (uint32_t)((ks << 1) + aHi) ^ xr;
            ldsm4(afr[p][ks], sbase + OFF_AST + (uint32_t)(p * 8192) + rowByteA + (ca << 4));
        }

    uint32_t nByte[2];
    #pragma unroll
    for (int np = 0; np < 2; np++)
        nByte[np] = (uint32_t)((colg * 32 + np * 16 + (lane & 7) + ((lane >> 4) << 3)) * 128);

    const int r0 = rowg * 16 + (lane >> 2);
    float zq0 = s_zsq[r0], zq1 = s_zsq[r0 + 8];

    float best[2] = {3.4e38f, 3.4e38f}, b2v[2] = {3.4e38f, 3.4e38f};
    int   bi[2] = {0, 0};

    #pragma unroll 1
    for (int t = 0; t < NTILES; ++t) {
        mbar_wait(mb0 + (t & 3) * 8, (uint32_t)((t >> 2) & 1));
        __syncthreads();   // all warps past iter t-1 => stage (t-1)&3 reusable
        if (tid == 0 && t + 3 < NTILES) {
            int s = (t + 3) & 3;
            mbar_expect_tx(mb0 + s * 8, TILE_BYTES);
            bulk_g2s(sbase + OFF_B + s * TILE_BYTES,
                     g_Bsw + (size_t)(t + 3) * TILE_BYTES, TILE_BYTES, mb0 + s * 8);
        }
        const uint32_t bb = sbase + OFF_B + (uint32_t)((t & 3) * TILE_BYTES);

        float acc[4][4];
        #pragma unroll
        for (int nt = 0; nt < 4; nt++)
            #pragma unroll
            for (int j = 0; j < 4; j++) acc[nt][j] = 0.f;

        #pragma unroll
        for (int ks = 0; ks < 4; ks++) {
            uint32_t bfr[2][4];
            const uint32_t cb = (uint32_t)((ks << 1) + bHi) ^ xr;
            #pragma unroll
            for (int np = 0; np < 2; np++)
                ldsm4(bfr[np], bb + nByte[np] + (cb << 4));
            #pragma unroll
            for (int p = 0; p < 2; p++)
                #pragma unroll
                for (int np = 0; np < 2; np++)
                    #pragma unroll
                    for (int j = 0; j < 2; j++)
                        mma16816(acc[np * 2 + j], afr[p][ks], &bfr[np][j * 2]);
        }

        // fold: dist = fmaf(-2,dot,zsq)+esq (ref rounding); branchless best/2nd
        #pragma unroll
        for (int nt = 0; nt < 4; nt++) {
            int col0 = t * 64 + colg * 32 + nt * 8 + (lane & 3) * 2;
            float e0 = s_esq[col0], e1 = s_esq[col0 + 1];
            float* c = acc[nt];
            float dv0 = fmaf(-2.f, c[0], zq0) + e0;
            float dv1 = fmaf(-2.f, c[1], zq0) + e1;
            float dv2 = fmaf(-2.f, c[2], zq1) + e0;
            float dv3 = fmaf(-2.f, c[3], zq1) + e1;
            b2v[0] = fminf(b2v[0], fmaxf(dv0, best[0]));
            bi[0]  = (dv0 < best[0]) ? col0 : bi[0];
            best[0] = fminf(best[0], dv0);
            b2v[0] = fminf(b2v[0], fmaxf(dv1, best[0]));
            bi[0]  = (dv1 < best[0]) ? (col0 + 1) : bi[0];
            best[0] = fminf(best[0], dv1);
            b2v[1] = fminf(b2v[1], fmaxf(dv2, best[1]));
            bi[1]  = (dv2 < best[1]) ? col0 : bi[1];
            best[1] = fminf(best[1], dv2);
            b2v[1] = fminf(b2v[1], fmaxf(dv3, best[1]));
            bi[1]  = (dv3 < best[1]) ? (col0 + 1) : bi[1];
            best[1] = fminf(best[1], dv3);
        }
    }

    // reduce over lane&3; lex (value,index) for best, 2-min merge for second
    #pragma unroll
    for (int i = 0; i < 2; i++) {
        float v = best[i], s2 = b2v[i]; int ix = bi[i];
        #pragma unroll
        for (int off = 1; off <= 2; off <<= 1) {
            float ov = __shfl_xor_sync(0xFFFFFFFFu, v, off);
            int   oi = __shfl_xor_sync(0xFFFFFFFFu, ix, off);
            float o2 = __shfl_xor_sync(0xFFFFFFFFu, s2, off);
            float hi = fmaxf(v, ov);
            s2 = fminf(fminf(s2, o2), hi);
            if (ov < v || (ov == v && oi < ix)) { v = ov; ix = oi; }
        }
        best[i] = v; bi[i] = ix; b2v[i] = s2;
    }
    if ((lane & 3) == 0) {
        #pragma unroll
        for (int i = 0; i < 2; i++) {
            int row = r0 + i * 8;
            ((float*)(smem + OFF_FBV))[colg * 64 + row] = best[i];
            ((int*)(smem + OFF_FBI))[colg * 64 + row] = bi[i];
            ((float*)(smem + OFF_FB2))[colg * 64 + row] = b2v[i];
        }
    }
    __syncthreads();
    if (tid < BM) {
        int row = tid;
        float v0 = ((float*)(smem + OFF_FBV))[row];
        float v1 = ((float*)(smem + OFF_FBV))[64 + row];
        int i0 = ((int*)(smem + OFF_FBI))[row];
        int i1 = ((int*)(smem + OFF_FBI))[64 + row];
        float s0 = ((float*)(smem + OFF_FB2))[row];
        float s1 = ((float*)(smem + OFF_FB2))[64 + row];
        float s2m = fminf(fminf(s0, s1), fmaxf(v0, v1));
        float vm; int pick;
        if (v1 < v0 || (v1 == v0 && i1 < i0)) { vm = v1; pick = i1; }
        else { vm = v0; pick = i0; }
        ((int*)(smem + OFF_SIDX))[row] = pick;
        unsigned flagw = __ballot_sync(0xFFFFFFFFu, (s2m - vm) < s_mgn[row]);
        if (lane == 0) ((unsigned*)(smem + OFF_FLAGW))[tid >> 5] = flagw;
    }
    __syncthreads();

    // ---- Rescue: flagged tokens get a bit-exact recompute ----
    int* sidx = (int*)(smem + OFF_SIDX);
    float* s_zvec = (float*)(smem + OFF_ZVEC);
    #pragma unroll 1
    for (int w = 0; w < 2; w++) {
        unsigned word = ((unsigned*)(smem + OFF_FLAGW))[w];
        while (word) {
            int r = __ffs(word) - 1;
            word &= word - 1;
            int m = w * 32 + r;
            if (tid < D_DIM) s_zvec[tid] = zb[(size_t)tid * TOKB + m];
            __syncthreads();
            float zsq_m = s_zsq[m];
            float acc4[4];
            #pragma unroll
            for (int q = 0; q < 4; q++) acc4[q] = 0.f;
            #pragma unroll 1
            for (int d = 0; d < D_DIM; d++) {       // sequential ascending d
                float zd = s_zvec[d];
                #pragma unroll
                for (int q = 0; q < 4; q++)
                    acc4[q] = fmaf(zd, g_embT[d * KC + q * 256 + tid], acc4[q]);
            }
            float bv = 3.4e38f; int bix = 0;
            #pragma unroll
            for (int q = 0; q < 4; q++) {           // ascending code per thread
                int c = q * 256 + tid;
                float dot = fminf(fmaxf(acc4[q], -CLAMPV), CLAMPV);
                float dist = fmaf(-2.f, dot, zsq_m) + s_esq[c];
                if (dist < bv) { bv = dist; bix = c; }
            }
            #pragma unroll
            for (int off = 16; off >= 1; off >>= 1) {
                float ov = __shfl_xor_sync(0xFFFFFFFFu, bv, off);
                int   oi = __shfl_xor_sync(0xFFFFFFFFu, bix, off);
                if (ov < bv || (ov == bv && oi < bix)) { bv = ov; bix = oi; }
            }
            if (lane == 0) {
                ((float*)(smem + OFF_REDV))[wid] = bv;
                ((int*)(smem + OFF_REDI))[wid] = bix;
            }
            __syncthreads();
            if (tid == 0) {
                float v = ((float*)(smem + OFF_REDV))[0];
                int ix = ((int*)(smem + OFF_REDI))[0];
                #pragma unroll
                for (int ww = 1; ww < 8; ww++) {
                    float ov = ((float*)(smem + OFF_REDV))[ww];
                    int oi = ((int*)(smem + OFF_REDI))[ww];
                    if (ov < v || (ov == v && oi < ix)) { v = ov; ix = oi; }
                }
                sidx[m] = ix;
            }
            __syncthreads();
        }
    }
    __syncthreads();

    if (tid < BM)
        out[(size_t)IDX_OFF + (size_t)b * TOKB + t0 + tid] = (float)sidx[tid];

    // epilogue: gather, z_q, loss
    float lsum = 0.f;
    #pragma unroll 4
    for (int i = tid; i < D_DIM * BM; i += 256) {
        int d = i >> 6, m = i & 63;
        float q = g_embT[d * KC + sidx[m]];
        float z = zb[(size_t)d * TOKB + m];
        float df = q - z;
        lsum += df * df;
        out[(size_t)b * D_DIM * TOKB + (size_t)d * TOKB + t0 + m] = q;
    }
    #pragma unroll
    for (int off = 16; off >= 1; off >>= 1)
        lsum += __shfl_xor_sync(0xFFFFFFFFu, lsum, off);
    if (lane == 0) ((float*)(smem + OFF_WSUM))[wid] = lsum;
    __syncthreads();
    if (tid == 0) {
        float s = 0.f;
        #pragma unroll
        for (int w = 0; w < 8; w++) s += ((float*)(smem + OFF_WSUM))[w];
        g_part[blockIdx.x] = s;
    }
    if (tid == 0) {
        #pragma unroll
        for (int s = 0; s < 4; s++)
            asm volatile("mbarrier.inval.shared.b64 [%0];" :: "r"(mb0 + s * 8) : "memory");
    }
}

// ---------------- Final loss reduction (1024 partials, 1 block) ------------
__global__ void vq_loss_kernel(float* __restrict__ out) {
    __shared__ float sh[32];
    int tid = threadIdx.x;
    float v = g_part[tid];
    #pragma unroll
    for (int off = 16; off >= 1; off >>= 1)
        v += __shfl_xor_sync(0xFFFFFFFFu, v, off);
    if ((tid & 31) == 0) sh[tid >> 5] = v;
    __syncthreads();
    if (tid == 0) {
        float total = 0.f;
        #pragma unroll
        for (int w = 0; w < 32; w++) total += sh[w];
        float mean = total / 4194304.0f;
        out[LOSS_OFF] = mean + 0.25f * mean;
    }
}

// ---------------------------------------------------------------------------
extern "C" void kernel_launch(void* const* d_in, const int* in_sizes, int n_in,
                              void* d_out, int out_size) {
    const float* z_e = (const float*)d_in[0];
    const float* emb = (const float*)d_in[1];
    if (n_in >= 2 && in_sizes[0] == KC * D_DIM) {
        z_e = (const float*)d_in[1];
        emb = (const float*)d_in[0];
    }
    float* out = (float*)d_out;
    (void)out_size;

    cudaFuncSetAttribute(vq_main_kernel,
                         cudaFuncAttributeMaxDynamicSharedMemorySize, SMEM_TOTAL);
    vq_prep_kernel<<<NTOK / 256, 256>>>(emb);
    vq_main_kernel<<<NBLK, 256, SMEM_TOTAL>>>(z_e, out);
    vq_loss_kernel<<<1, NBLK>>>(out);
}

// round 13
// speedup vs baseline: 3.5771x; 3.5771x over previous
#include <cuda_runtime.h>
#include <cuda_bf16.h>
#include <cstdint>
#include <cstddef>

#define D_DIM   64
#define KC      1024
#define TOKB    4096
#define NTOK    65536
#define BM      64            // tokens per CTA
#define NTILES  16
#define NBLK    (NTOK / BM)   // 1024
#define LOSS_OFF 4194304
#define IDX_OFF  4194305
#define CLAMPV  1.0e6f
#define MARGIN  1.0e-5f
#define TILE_BYTES 16384      // one B tile: 2 parts x 64 codes x 128B

// smem layout (bytes)
#define OFF_ZSQ   0        // 64*4 -> 256
#define OFF_ESQ   256      // 1024*4 -> 4352
#define OFF_FBV   4352     // 2*64*4 -> 4864
#define OFF_FBI   4864     // -> 5376
#define OFF_FB2   5376     // -> 5888
#define OFF_SIDX  5888     // 64*4 -> 6144
#define OFF_WSUM  6144     // 8*4
#define OFF_ZVEC  6208     // 64*4 -> 6464
#define OFF_REDV  6464     // 8*4
#define OFF_REDI  6496     // 8*4
#define OFF_FLAGW 6528     // 2*4
#define OFF_MBAR  6592     // 4 mbarriers * 8B = 32
#define OFF_AST   8192     // 2 parts * 8192 = 16384
#define OFF_B     24576    // 4 stages * 16384 = 65536
#define SMEM_TOTAL 90112

__device__ float g_embT[D_DIM * KC];
__device__ float g_esq[KC];
__device__ float g_part[NBLK];
// Pre-swizzled B tile images: [tile(16)][part(2)][row(64)*128B], ldmatrix-ready
__device__ __align__(128) unsigned char g_Bsw[NTILES * TILE_BYTES];

// ---------------- helpers ----------------
__device__ __forceinline__ uint32_t smem_u32(const void* p) {
    uint32_t a;
    asm("{ .reg .u64 t; cvta.to.shared.u64 t, %1; cvt.u32.u64 %0, t; }" : "=r"(a) : "l"(p));
    return a;
}
__device__ __forceinline__ void split2(float z, __nv_bfloat16& a, __nv_bfloat16& b) {
    a = __float2bfloat16(z);
    b = __float2bfloat16(z - __bfloat162float(a));
}
__device__ __forceinline__ void ldsm4(uint32_t* r, uint32_t a) {
    asm volatile("ldmatrix.sync.aligned.m8n8.x4.shared.b16 {%0,%1,%2,%3}, [%4];"
                 : "=r"(r[0]), "=r"(r[1]), "=r"(r[2]), "=r"(r[3]) : "r"(a));
}
__device__ __forceinline__ void mma16816(float* c, const uint32_t* a, const uint32_t* b) {
    asm volatile(
        "mma.sync.aligned.m16n8k16.row.col.f32.bf16.bf16.f32 "
        "{%0,%1,%2,%3}, {%4,%5,%6,%7}, {%8,%9}, {%0,%1,%2,%3};"
        : "+f"(c[0]), "+f"(c[1]), "+f"(c[2]), "+f"(c[3])
        : "r"(a[0]), "r"(a[1]), "r"(a[2]), "r"(a[3]), "r"(b[0]), "r"(b[1]));
}
__device__ __forceinline__ void mbar_init(uint32_t mbar, uint32_t cnt) {
    asm volatile("mbarrier.init.shared.b64 [%0], %1;" :: "r"(mbar), "r"(cnt) : "memory");
}
__device__ __forceinline__ void mbar_expect_tx(uint32_t mbar, uint32_t bytes) {
    asm volatile("mbarrier.arrive.expect_tx.shared.b64 _, [%0], %1;"
                 :: "r"(mbar), "r"(bytes) : "memory");
}
__device__ __forceinline__ void bulk_g2s(uint32_t dst, const void* src, uint32_t bytes,
                                         uint32_t mbar) {
    asm volatile(
        "cp.async.bulk.shared::cta.global.mbarrier::complete_tx::bytes [%0], [%1], %2, [%3];"
        :: "r"(dst), "l"(src), "r"(bytes), "r"(mbar) : "memory");
}
__device__ __forceinline__ void mbar_wait(uint32_t mbar, uint32_t parity) {
    asm volatile(
        "{\n\t.reg .pred P;\n\t"
        "W_%=:\n\tmbarrier.try_wait.parity.acquire.cta.shared::cta.b64 P, [%0], %1, 0x989680;\n\t"
        "@P bra.uni D_%=;\n\tbra.uni W_%=;\n\tD_%=:\n\t}"
        :: "r"(mbar), "r"(parity) : "memory");
}

// ---------------- Prep: transpose, norms, bf16 2-split into swizzled tiles --
__global__ void vq_prep_kernel(const float* __restrict__ emb) {
    int idx = blockIdx.x * blockDim.x + threadIdx.x;   // 0..65535
    int n = idx >> 6, d = idx & 63;
    float v = emb[idx];                 // emb[n*64 + d] (coalesced)
    g_embT[d * KC + n] = v;
    __nv_bfloat16 a, b;
    split2(v, a, b);
    int t = n >> 6, nl = n & 63;
    uint32_t off = (uint32_t)(t * TILE_BYTES + nl * 128
                 + (((d >> 3) ^ (nl & 7)) << 4) + (d & 7) * 2);
    *(__nv_bfloat16*)(g_Bsw + off) = a;             // part 0
    *(__nv_bfloat16*)(g_Bsw + off + 8192) = b;      // part 1
    if (idx < KC) {
        const float4* e4 = (const float4*)(emb + (size_t)idx * D_DIM);
        float s = 0.f;
        #pragma unroll
        for (int i = 0; i < 16; i++) {
            float4 w = e4[i];
            s += w.x * w.x + w.y * w.y + w.z * w.z + w.w * w.w;
        }
        g_esq[idx] = fminf(s, CLAMPV);
    }
}

// ---------------- Main: bulk-fed mma.sync GEMM + argmin + rescue ----------
__global__ void __launch_bounds__(256, 2) vq_main_kernel(
    const float* __restrict__ z_e, float* __restrict__ out)
{
    extern __shared__ __align__(128) unsigned char smem[];
    const uint32_t sbase = smem_u32(smem);
    const int tid = threadIdx.x, wid = tid >> 5, lane = tid & 31;
    const int rowg = wid >> 1;            // 0..3 : 16 rows each
    const int colg = wid & 1;             // 0..1 : 32 cols each
    const int b = blockIdx.x >> 6, t0 = (blockIdx.x & 63) << 6;
    const float* zb = z_e + (size_t)b * D_DIM * TOKB + t0;

    float* s_zsq = (float*)(smem + OFF_ZSQ);
    float* s_esq = (float*)(smem + OFF_ESQ);
    const uint32_t mb0 = sbase + OFF_MBAR;

    if (tid == 0) {
        #pragma unroll
        for (int s = 0; s < 4; s++) mbar_init(mb0 + s * 8, 1);
    }
    __syncthreads();
    if (tid == 0) {
        #pragma unroll
        for (int p = 0; p < 3; p++) {
            mbar_expect_tx(mb0 + p * 8, TILE_BYTES);
            bulk_g2s(sbase + OFF_B + p * TILE_BYTES, g_Bsw + (size_t)p * TILE_BYTES,
                     TILE_BYTES, mb0 + p * 8);
        }
    }

    // A staging: 2 bf16 parts, [m(64)][k(64)] 128B rows, 16B-chunk XOR swizzle
    for (int i = tid; i < D_DIM * BM; i += 256) {
        int m = i & 63, d = i >> 6;
        __nv_bfloat16 va, vb;
        split2(zb[(size_t)d * TOKB + m], va, vb);
        uint32_t off = (uint32_t)(m * 128 + (((d >> 3) ^ (m & 7)) << 4) + (d & 7) * 2);
        *(__nv_bfloat16*)(smem + OFF_AST + off) = va;
        *(__nv_bfloat16*)(smem + OFF_AST + 8192 + off) = vb;
    }
    if (tid < BM) {   // exact ref zsq: sequential fp32 fma over d
        float s = 0.f;
        for (int d = 0; d < D_DIM; d++) {
            float z = zb[(size_t)d * TOKB + tid];
            s = fmaf(z, z, s);
        }
        s_zsq[tid] = fminf(s, CLAMPV);
    }
    for (int i = tid; i < KC; i += 256) s_esq[i] = g_esq[i];
    __syncthreads();

    // ---- Hoist A fragments (tile-invariant): afr[part][ks][4]
    const uint32_t xr  = (uint32_t)(lane & 7);
    const uint32_t aHi = (uint32_t)(lane >> 4);
    const uint32_t bHi = (uint32_t)((lane >> 3) & 1);
    const uint32_t rowByteA = (uint32_t)((rowg * 16 + (lane & 15)) * 128);
    uint32_t afr[2][4][4];
    #pragma unroll
    for (int p = 0; p < 2; p++)
        #pragma unroll
        for (int ks = 0; ks < 4; ks++) {
            uint32_t ca = (uint32_t)((ks << 1) + aHi) ^ xr;
            ldsm4(afr[p][ks], sbase + OFF_AST + (uint32_t)(p * 8192) + rowByteA + (ca << 4));
        }

    uint32_t nByte[2];
    #pragma unroll
    for (int np = 0; np < 2; np++)
        nByte[np] = (uint32_t)((colg * 32 + np * 16 + (lane & 7) + ((lane >> 4) << 3)) * 128);

    const int r0 = rowg * 16 + (lane >> 2);
    float zq0 = s_zsq[r0], zq1 = s_zsq[r0 + 8];

    float best[2] = {3.4e38f, 3.4e38f}, b2v[2] = {3.4e38f, 3.4e38f};
    int   bi[2] = {0, 0};

    #pragma unroll 1
    for (int t = 0; t < NTILES; ++t) {
        mbar_wait(mb0 + (t & 3) * 8, (uint32_t)((t >> 2) & 1));
        __syncthreads();   // all warps past iter t-1 => stage (t-1)&3 reusable
        if (tid == 0 && t + 3 < NTILES) {
            int s = (t + 3) & 3;
            mbar_expect_tx(mb0 + s * 8, TILE_BYTES);
            bulk_g2s(sbase + OFF_B + s * TILE_BYTES,
                     g_Bsw + (size_t)(t + 3) * TILE_BYTES, TILE_BYTES, mb0 + s * 8);
        }
        const uint32_t bb = sbase + OFF_B + (uint32_t)((t & 3) * TILE_BYTES);

        float acc[4][4];
        #pragma unroll
        for (int nt = 0; nt < 4; nt++)
            #pragma unroll
            for (int j = 0; j < 4; j++) acc[nt][j] = 0.f;

        #pragma unroll
        for (int ks = 0; ks < 4; ks++) {
            uint32_t bfr[2][2][4];
            const uint32_t cb = (uint32_t)((ks << 1) + bHi) ^ xr;
            #pragma unroll
            for (int p = 0; p < 2; p++)
                #pragma unroll
                for (int np = 0; np < 2; np++)
                    ldsm4(bfr[p][np], bb + (uint32_t)(p * 8192) + nByte[np] + (cb << 4));
            const int PA[3] = {0, 1, 0};
            const int PB[3] = {0, 0, 1};
            #pragma unroll
            for (int s = 0; s < 3; s++)
                #pragma unroll
                for (int np = 0; np < 2; np++)
                    #pragma unroll
                    for (int j = 0; j < 2; j++)
                        mma16816(acc[np * 2 + j], afr[PA[s]][ks], &bfr[PB[s]][np][j * 2]);
        }

        // fold: dist = fmaf(-2,dot,zsq)+esq (ref rounding); branchless best/2nd
        #pragma unroll
        for (int nt = 0; nt < 4; nt++) {
            int col0 = t * 64 + colg * 32 + nt * 8 + (lane & 3) * 2;
            float e0 = s_esq[col0], e1 = s_esq[col0 + 1];
            float* c = acc[nt];
            float dv0 = fmaf(-2.f, c[0], zq0) + e0;
            float dv1 = fmaf(-2.f, c[1], zq0) + e1;
            float dv2 = fmaf(-2.f, c[2], zq1) + e0;
            float dv3 = fmaf(-2.f, c[3], zq1) + e1;
            b2v[0] = fminf(b2v[0], fmaxf(dv0, best[0]));
            bi[0]  = (dv0 < best[0]) ? col0 : bi[0];
            best[0] = fminf(best[0], dv0);
            b2v[0] = fminf(b2v[0], fmaxf(dv1, best[0]));
            bi[0]  = (dv1 < best[0]) ? (col0 + 1) : bi[0];
            best[0] = fminf(best[0], dv1);
            b2v[1] = fminf(b2v[1], fmaxf(dv2, best[1]));
            bi[1]  = (dv2 < best[1]) ? col0 : bi[1];
            best[1] = fminf(best[1], dv2);
            b2v[1] = fminf(b2v[1], fmaxf(dv3, best[1]));
            bi[1]  = (dv3 < best[1]) ? (col0 + 1) : bi[1];
            best[1] = fminf(best[1], dv3);
        }
    }

    // reduce over lane&3; lex (value,index) for best, 2-min merge for second
    #pragma unroll
    for (int i = 0; i < 2; i++) {
        float v = best[i], s2 = b2v[i]; int ix = bi[i];
        #pragma unroll
        for (int off = 1; off <= 2; off <<= 1) {
            float ov = __shfl_xor_sync(0xFFFFFFFFu, v, off);
            int   oi = __shfl_xor_sync(0xFFFFFFFFu, ix, off);
            float o2 = __shfl_xor_sync(0xFFFFFFFFu, s2, off);
            float hi = fmaxf(v, ov);
            s2 = fminf(fminf(s2, o2), hi);
            if (ov < v || (ov == v && oi < ix)) { v = ov; ix = oi; }
        }
        best[i] = v; bi[i] = ix; b2v[i] = s2;
    }
    if ((lane & 3) == 0) {
        #pragma unroll
        for (int i = 0; i < 2; i++) {
            int row = r0 + i * 8;
            ((float*)(smem + OFF_FBV))[colg * 64 + row] = best[i];
            ((int*)(smem + OFF_FBI))[colg * 64 + row] = bi[i];
            ((float*)(smem + OFF_FB2))[colg * 64 + row] = b2v[i];
        }
    }
    __syncthreads();
    if (tid < BM) {
        int row = tid;
        float v0 = ((float*)(smem + OFF_FBV))[row];
        float v1 = ((float*)(smem + OFF_FBV))[64 + row];
        int i0 = ((int*)(smem + OFF_FBI))[row];
        int i1 = ((int*)(smem + OFF_FBI))[64 + row];
        float s0 = ((float*)(smem + OFF_FB2))[row];
        float s1 = ((float*)(smem + OFF_FB2))[64 + row];
        float s2m = fminf(fminf(s0, s1), fmaxf(v0, v1));
        float vm; int pick;
        if (v1 < v0 || (v1 == v0 && i1 < i0)) { vm = v1; pick = i1; }
        else { vm = v0; pick = i0; }
        ((int*)(smem + OFF_SIDX))[row] = pick;
        unsigned flagw = __ballot_sync(0xFFFFFFFFu, (s2m - vm) < MARGIN);
        if (lane == 0) ((unsigned*)(smem + OFF_FLAGW))[tid >> 5] = flagw;
    }
    __syncthreads();

    // ---- Rescue: near-tie tokens get a bit-exact recompute ----
    int* sidx = (int*)(smem + OFF_SIDX);
    float* s_zvec = (float*)(smem + OFF_ZVEC);
    #pragma unroll 1
    for (int w = 0; w < 2; w++) {
        unsigned word = ((unsigned*)(smem + OFF_FLAGW))[w];
        while (word) {
            int r = __ffs(word) - 1;
            word &= word - 1;
            int m = w * 32 + r;
            if (tid < D_DIM) s_zvec[tid] = zb[(size_t)tid * TOKB + m];
            __syncthreads();
            float zsq_m = s_zsq[m];
            float acc4[4];
            #pragma unroll
            for (int q = 0; q < 4; q++) acc4[q] = 0.f;
            #pragma unroll 4
            for (int d = 0; d < D_DIM; d++) {       // sequential ascending d
                float zd = s_zvec[d];
                #pragma unroll
                for (int q = 0; q < 4; q++)
                    acc4[q] = fmaf(zd, g_embT[d * KC + q * 256 + tid], acc4[q]);
            }
            float bv = 3.4e38f; int bix = 0;
            #pragma unroll
            for (int q = 0; q < 4; q++) {           // ascending code per thread
                int c = q * 256 + tid;
                float dot = fminf(fmaxf(acc4[q], -CLAMPV), CLAMPV);
                float dist = fmaf(-2.f, dot, zsq_m) + s_esq[c];
                if (dist < bv) { bv = dist; bix = c; }
            }
            #pragma unroll
            for (int off = 16; off >= 1; off >>= 1) {
                float ov = __shfl_xor_sync(0xFFFFFFFFu, bv, off);
                int   oi = __shfl_xor_sync(0xFFFFFFFFu, bix, off);
                if (ov < bv || (ov == bv && oi < bix)) { bv = ov; bix = oi; }
            }
            if (lane == 0) {
                ((float*)(smem + OFF_REDV))[wid] = bv;
                ((int*)(smem + OFF_REDI))[wid] = bix;
            }
            __syncthreads();
            if (tid == 0) {
                float v = ((float*)(smem + OFF_REDV))[0];
                int ix = ((int*)(smem + OFF_REDI))[0];
                #pragma unroll
                for (int ww = 1; ww < 8; ww++) {
                    float ov = ((float*)(smem + OFF_REDV))[ww];
                    int oi = ((int*)(smem + OFF_REDI))[ww];
                    if (ov < v || (ov == v && oi < ix)) { v = ov; ix = oi; }
                }
                sidx[m] = ix;
            }
            __syncthreads();
        }
    }
    __syncthreads();

    if (tid < BM)
        out[(size_t)IDX_OFF + (size_t)b * TOKB + t0 + tid] = (float)sidx[tid];

    // epilogue: gather, z_q, loss
    float lsum = 0.f;
    #pragma unroll 4
    for (int i = tid; i < D_DIM * BM; i += 256) {
        int d = i >> 6, m = i & 63;
        float q = g_embT[d * KC + sidx[m]];
        float z = zb[(size_t)d * TOKB + m];
        float df = q - z;
        lsum += df * df;
        out[(size_t)b * D_DIM * TOKB + (size_t)d * TOKB + t0 + m] = q;
    }
    #pragma unroll
    for (int off = 16; off >= 1; off >>= 1)
        lsum += __shfl_xor_sync(0xFFFFFFFFu, lsum, off);
    if (lane == 0) ((float*)(smem + OFF_WSUM))[wid] = lsum;
    __syncthreads();
    if (tid == 0) {
        float s = 0.f;
        #pragma unroll
        for (int w = 0; w < 8; w++) s += ((float*)(smem + OFF_WSUM))[w];
        g_part[blockIdx.x] = s;
    }
    if (tid == 0) {
        #pragma unroll
        for (int s = 0; s < 4; s++)
            asm volatile("mbarrier.inval.shared.b64 [%0];" :: "r"(mb0 + s * 8) : "memory");
    }
}

// ---------------- Final loss reduction (1024 partials, 1 block) ------------
__global__ void vq_loss_kernel(float* __restrict__ out) {
    __shared__ float sh[32];
    int tid = threadIdx.x;
    float v = g_part[tid];
    #pragma unroll
    for (int off = 16; off >= 1; off >>= 1)
        v += __shfl_xor_sync(0xFFFFFFFFu, v, off);
    if ((tid & 31) == 0) sh[tid >> 5] = v;
    __syncthreads();
    if (tid == 0) {
        float total = 0.f;
        #pragma unroll
        for (int w = 0; w < 32; w++) total += sh[w];
        float mean = total / 4194304.0f;
        out[LOSS_OFF] = mean + 0.25f * mean;
    }
}

// ---------------------------------------------------------------------------
extern "C" void kernel_launch(void* const* d_in, const int* in_sizes, int n_in,
                              void* d_out, int out_size) {
    const float* z_e = (const float*)d_in[0];
    const float* emb = (const float*)d_in[1];
    if (n_in >= 2 && in_sizes[0] == KC * D_DIM) {
        z_e = (const float*)d_in[1];
        emb = (const float*)d_in[0];
    }
    float* out = (float*)d_out;
    (void)out_size;

    cudaFuncSetAttribute(vq_main_kernel,
                         cudaFuncAttributeMaxDynamicSharedMemorySize, SMEM_TOTAL);
    vq_prep_kernel<<<NTOK / 256, 256>>>(emb);
    vq_main_kernel<<<NBLK, 256, SMEM_TOTAL>>>(z_e, out);
    vq_loss_kernel<<<1, NBLK>>>(out);
}